// round 15
// baseline (speedup 1.0000x reference)
#include <cuda_runtime.h>
#include <cuda_fp16.h>
#include <mma.h>
#include <math.h>
#include <stdint.h>

using namespace nvcuda;

#define BB   128
#define TT   65536
#define DELTA 16
#define LS   32
#define HID  8
#define GH   64
#define ODIM 16
#define FF   4095
#define CCH  64
#define NCH  (TT/CCH)

typedef unsigned int u32;

// ---------------- device scratch ----------------
__device__ float d_As[(size_t)BB * FF * HID];
__device__ float d_gs[(size_t)BB * FF * HID];
__device__ float d_P [BB * NCH * HID];
__device__ float d_c [BB * NCH * HID];
__device__ float d_H0[BB * NCH * HID];
__device__ float d_cpar[GH * 8];

__device__ __forceinline__ float sigf(float v) {
    return __fdividef(1.0f, 1.0f + __expf(-v));
}
__device__ __forceinline__ __half2 h2tanh_ap(__half2 v) {
    u32 r, a = *(u32*)&v;
    asm("tanh.approx.f16x2 %0, %1;" : "=r"(r) : "r"(a));
    return *(__half2*)&r;
}

// r,z entries pre-scaled by 0.5 so sigmoid = 0.5*tanh(pre)+0.5 needs no extra scale
__global__ void init_cpar_kernel(const float* __restrict__ w_ih,
                                 const float* __restrict__ b_ih,
                                 const float* __restrict__ b_hh) {
    int j = threadIdx.x;
    if (j < GH) {
        d_cpar[j*8+0] = 0.5f * w_ih[j];
        d_cpar[j*8+1] = 0.5f * w_ih[GH + j];
        d_cpar[j*8+2] = w_ih[2*GH + j];
        d_cpar[j*8+3] = 0.5f * (b_ih[j]      + b_hh[j]);
        d_cpar[j*8+4] = 0.5f * (b_ih[GH + j] + b_hh[GH + j]);
        d_cpar[j*8+5] = b_ih[2*GH + j];
        d_cpar[j*8+6] = b_hh[2*GH + j];
        d_cpar[j*8+7] = 0.0f;
    }
}

// ---------------- smem layout (bytes) ----------------
#define LDW   72
#define LDHH  264
#define LDS_X 33
#define SM_WHI  0
#define SM_H    (SM_WHI + 192*LDW*2)         // 27648
#define SM_XS   (SM_H + 64*LDHH*2)           // 61440
#define SM_CPAR (SM_XS + 256*LDS_X*4)        // 95232
#define SM_WSL  (SM_CPAR + GH*8*4)           // 97280
#define SM_BSL  (SM_WSL + ODIM*GH*4)         // 101376
#define SM_BYTES (SM_BSL + 64)               // 101440  (x2 fits 228KB/SM)

// grid = 2048 CTAs, 256 threads, 2 CTAs/SM. CTA covers frames {2c, 2c+1} x 128 rows.
__global__ void __launch_bounds__(256, 2) slow_wmma_kernel(
    const float* __restrict__ x,
    const float* __restrict__ w_hh,
    const float* __restrict__ w_sl,
    const float* __restrict__ b_sl)
{
    extern __shared__ char sm[];
    const int tid  = threadIdx.x;
    const int wid  = tid >> 5;
    const int f0   = blockIdx.x * 2;
    const int cb   = wid * 32;

    __half* WHI = (__half*)(sm + SM_WHI);
    __half* HS  = (__half*)(sm + SM_H);
    float* xs     = (float*)(sm + SM_XS);
    float* cparsm = (float*)(sm + SM_CPAR);
    float* wslsm  = (float*)(sm + SM_WSL);
    float* bslsm  = (float*)(sm + SM_BSL);

    // ---- probe wmma accumulator element->(row,col) mapping ----
    int jm[8], cm[8];
    {
        __half* pA = (__half*)(sm + SM_XS);
        __half* pB = pA + 256;
        if (tid < 256) {
            int r = tid >> 4, k = tid & 15;
            pA[tid] = __float2half_rn(r == k ? 1.0f : 0.0f);
            pB[tid] = __float2half_rn((float)tid);
        }
        __syncthreads();
        wmma::fragment<wmma::matrix_a, 16,16,16, __half, wmma::row_major> pa;
        wmma::fragment<wmma::matrix_b, 16,16,16, __half, wmma::row_major> pb;
        wmma::fragment<wmma::accumulator, 16,16,16, float> pc;
        wmma::load_matrix_sync(pa, pA, 16);
        wmma::load_matrix_sync(pb, pB, 16);
        wmma::fill_fragment(pc, 0.0f);
        wmma::mma_sync(pc, pa, pb, pc);
#pragma unroll
        for (int e = 0; e < 8; e++) {
            int v = (int)(pc.x[e] + 0.5f);
            jm[e] = v >> 4;
            cm[e] = v & 15;
        }
        __syncthreads();
    }

    // ---- prologue ----
    // W rows for r,z gates (g<128) scaled by 0.5 to fold sigmoid's input scale
    for (int i = tid; i < 192 * GH; i += 256) {
        int g = i >> 6, k = i & 63;
        float v = w_hh[i];
        if (g < 128) v *= 0.5f;
        WHI[g * LDW + k] = __float2half_rn(v);
    }
    for (int i = tid; i < (64 * LDHH * 2) / 4; i += 256)
        ((u32*)(sm + SM_H))[i] = 0u;
    {
        int c = tid;
        int b = c & 127;
        int f = f0 + (c >> 7); if (f > FF - 1) f = FF - 1;
        const float* xp = x + (size_t)b * TT + (size_t)f * DELTA;
#pragma unroll
        for (int t = 0; t < LS; t++) xs[c * LDS_X + t] = xp[t];
    }
    for (int i = tid; i < GH * 8;    i += 256) cparsm[i] = d_cpar[i];
    for (int i = tid; i < ODIM * GH; i += 256) wslsm[i]  = w_sl[i];
    if (tid < ODIM) bslsm[tid] = b_sl[tid];
    __syncthreads();

    const __half2 h05 = __floats2half2_rn(0.5f, 0.5f);

    // ---- 32 GRU steps ----
#pragma unroll 1
    for (int t = 0; t < LS; t++) {
        float xts[16];
#pragma unroll
        for (int e = 0; e < 8; e++) {
            xts[e]     = xs[(cb + cm[e]) * LDS_X + t];
            xts[8 + e] = xs[(cb + 16 + cm[e]) * LDS_X + t];
        }

        wmma::fragment<wmma::matrix_b, 16,16,16, __half, wmma::row_major> bF[4][2];
#pragma unroll
        for (int kt = 0; kt < 4; kt++)
#pragma unroll
            for (int nt = 0; nt < 2; nt++)
                wmma::load_matrix_sync(bF[kt][nt], HS + (size_t)(kt*16) * LDHH + cb + nt*16, LDHH);

#pragma unroll 1
        for (int mg = 0; mg < 4; mg++) {
            wmma::fragment<wmma::accumulator, 16,16,16, float> acc[3][2];
#pragma unroll
            for (int kind = 0; kind < 3; kind++)
#pragma unroll
                for (int nt = 0; nt < 2; nt++)
                    wmma::fill_fragment(acc[kind][nt], 0.0f);

#pragma unroll
            for (int kind = 0; kind < 3; kind++) {
                const int mi = kind * 4 + mg;
#pragma unroll
                for (int kt = 0; kt < 4; kt++) {
                    wmma::fragment<wmma::matrix_a, 16,16,16, __half, wmma::row_major> aHI;
                    wmma::load_matrix_sync(aHI, WHI + (size_t)(mi*16) * LDW + kt*16, LDW);
                    wmma::mma_sync(acc[kind][0], aHI, bF[kt][0], acc[kind][0]);
                    wmma::mma_sync(acc[kind][1], aHI, bF[kt][1], acc[kind][1]);
                }
            }

            // fragment-direct epilogue; gates paired across nt in f16x2 MUFU
#pragma unroll
            for (int e = 0; e < 8; e++) {
                const int j = mg * 16 + jm[e];
                const float4 c0 = ((const float4*)(cparsm + j * 8))[0];
                const float4 c1 = ((const float4*)(cparsm + j * 8))[1];
                const int ca = cb + cm[e];
                const int cn = cb + 16 + cm[e];
                const float xt0 = xts[e];
                const float xt1 = xts[8 + e];

                float ho0 = __half2float(HS[(size_t)j * LDHH + ca]);
                float ho1 = __half2float(HS[(size_t)j * LDHH + cn]);

                // r,z: pre-activations already 0.5-scaled via W/cpar
                __half2 tr = h2tanh_ap(__floats2half2_rn(
                    acc[0][0].x[e] + fmaf(xt0, c0.x, c0.w),
                    acc[0][1].x[e] + fmaf(xt1, c0.x, c0.w)));
                __half2 tz = h2tanh_ap(__floats2half2_rn(
                    acc[1][0].x[e] + fmaf(xt0, c0.y, c1.x),
                    acc[1][1].x[e] + fmaf(xt1, c0.y, c1.x)));
                __half2 sr = __hfma2(tr, h05, h05);
                __half2 sz = __hfma2(tz, h05, h05);
                float r0 = __low2float(sr), r1 = __high2float(sr);
                float z0 = __low2float(sz), z1 = __high2float(sz);

                __half2 tn = h2tanh_ap(__floats2half2_rn(
                    fmaf(xt0, c0.z, c1.y) + r0 * (acc[2][0].x[e] + c1.z),
                    fmaf(xt1, c0.z, c1.y) + r1 * (acc[2][1].x[e] + c1.z)));
                float n0 = __low2float(tn), n1 = __high2float(tn);

                float h0 = n0 + z0 * (ho0 - n0);
                float h1 = n1 + z1 * (ho1 - n1);

                HS[(size_t)j * LDHH + ca] = __float2half_rn(h0);
                HS[(size_t)j * LDHH + cn] = __float2half_rn(h1);
            }
        }
        __syncwarp();
    }

    // ---- final projection (accurate sigmoid) ----
    {
        const int c = tid;
        const int b = c & 127;
        const int f = f0 + (c >> 7);
        if (f < FF) {
            float hv[GH];
#pragma unroll
            for (int k = 0; k < GH; k++)
                hv[k] = __half2float(HS[(size_t)k * LDHH + c]);
            const size_t ob = ((size_t)b * FF + f) * HID;
#pragma unroll 1
            for (int o = 0; o < HID; o++) {
                float a0 = bslsm[o];
                float a1 = bslsm[HID + o];
#pragma unroll
                for (int k = 0; k < GH; k++) {
                    a0 = fmaf(wslsm[o * GH + k], hv[k], a0);
                    a1 = fmaf(wslsm[(HID + o) * GH + k], hv[k], a1);
                }
                d_As[ob + o] = sigf(a0);
                d_gs[ob + o] = a1;
            }
        }
    }
}

// ---------------- fast branch ----------------
__global__ void __launch_bounds__(256) pass1_kernel(
    const float* __restrict__ x, const float* __restrict__ w_in)
{
    int q = blockIdx.x * blockDim.x + threadIdx.x;
    if (q >= BB * NCH) return;
    int b = q / NCH, ch = q % NCH;
    float win[HID], P[HID], c[HID];
#pragma unroll
    for (int i = 0; i < HID; i++) { win[i] = w_in[i]; P[i] = 1.0f; c[i] = 0.0f; }
    const int t0 = ch * CCH;
    const float* xb = x + (size_t)b * TT;
#pragma unroll 1
    for (int blk = 0; blk < CCH / 16; blk++) {
        int t = t0 + blk * 16;
        int j = (t >> 4) - 1; if (j < 0) j = 0;
        const float4* ap = (const float4*)(d_As + ((size_t)b * FF + j) * HID);
        const float4* gp = (const float4*)(d_gs + ((size_t)b * FF + j) * HID);
        float4 Aa = ap[0], Ab = ap[1], ga = gp[0], gb2 = gp[1];
        float A[HID] = {Aa.x, Aa.y, Aa.z, Aa.w, Ab.x, Ab.y, Ab.z, Ab.w};
        float g[HID] = {ga.x, ga.y, ga.z, ga.w, gb2.x, gb2.y, gb2.z, gb2.w};
        float wg[HID], a16[HID];
#pragma unroll
        for (int i = 0; i < HID; i++) {
            wg[i] = win[i] * g[i];
            float a2 = A[i]*A[i], a4 = a2*a2, a8 = a4*a4;
            a16[i] = a8*a8;
        }
        const float4* xv = (const float4*)(xb + t);
#pragma unroll
        for (int s4 = 0; s4 < 4; s4++) {
            float4 xq = xv[s4];
            float xsv[4] = {xq.x, xq.y, xq.z, xq.w};
#pragma unroll
            for (int s = 0; s < 4; s++)
#pragma unroll
                for (int i = 0; i < HID; i++)
                    c[i] = fmaf(A[i], c[i], xsv[s] * wg[i]);
        }
#pragma unroll
        for (int i = 0; i < HID; i++) P[i] *= a16[i];
    }
    const size_t base = ((size_t)b * NCH + ch) * HID;
#pragma unroll
    for (int i = 0; i < HID; i++) { d_P[base + i] = P[i]; d_c[base + i] = c[i]; }
}

__global__ void __launch_bounds__(256) scan_kernel() {
    int gw   = (blockIdx.x * blockDim.x + threadIdx.x) >> 5;
    int lane = threadIdx.x & 31;
    int b = gw >> 3, i = gw & 7;
    const int S = NCH / 32;
    float P[S], c[S];
#pragma unroll
    for (int s = 0; s < S; s++) {
        size_t idx = ((size_t)b * NCH + (lane * S + s)) * HID + i;
        P[s] = d_P[idx]; c[s] = d_c[idx];
    }
    float Pt = 1.0f, ct = 0.0f;
#pragma unroll
    for (int s = 0; s < S; s++) { ct = fmaf(P[s], ct, c[s]); Pt *= P[s]; }
#pragma unroll
    for (int off = 1; off < 32; off <<= 1) {
        float Pp = __shfl_up_sync(0xffffffffu, Pt, off);
        float cp = __shfl_up_sync(0xffffffffu, ct, off);
        if (lane >= off) { ct = fmaf(Pt, cp, ct); Pt *= Pp; }
    }
    float h = __shfl_up_sync(0xffffffffu, ct, 1);
    if (lane == 0) h = 0.0f;
#pragma unroll
    for (int s = 0; s < S; s++) {
        size_t idx = ((size_t)b * NCH + (lane * S + s)) * HID + i;
        d_H0[idx] = h;
        h = fmaf(P[s], h, c[s]);
    }
}

__global__ void __launch_bounds__(256) pass2_kernel(
    const float* __restrict__ x, const float* __restrict__ w_in,
    const float* __restrict__ w_out, float* __restrict__ y)
{
    int q = blockIdx.x * blockDim.x + threadIdx.x;
    if (q >= BB * NCH) return;
    int b = q / NCH, ch = q % NCH;
    float win[HID], wo[HID], h[HID];
#pragma unroll
    for (int i = 0; i < HID; i++) {
        win[i] = w_in[i]; wo[i] = w_out[i];
        h[i] = d_H0[((size_t)b * NCH + ch) * HID + i];
    }
    const int t0 = ch * CCH;
    const float* xb = x + (size_t)b * TT;
    float* yb = y + (size_t)b * TT;
#pragma unroll 1
    for (int blk = 0; blk < CCH / 16; blk++) {
        int t = t0 + blk * 16;
        int j = (t >> 4) - 1; if (j < 0) j = 0;
        const float4* ap = (const float4*)(d_As + ((size_t)b * FF + j) * HID);
        const float4* gp = (const float4*)(d_gs + ((size_t)b * FF + j) * HID);
        float4 Aa = ap[0], Ab = ap[1], ga = gp[0], gb2 = gp[1];
        float A[HID] = {Aa.x, Aa.y, Aa.z, Aa.w, Ab.x, Ab.y, Ab.z, Ab.w};
        float g[HID] = {ga.x, ga.y, ga.z, ga.w, gb2.x, gb2.y, gb2.z, gb2.w};
        float wg[HID];
#pragma unroll
        for (int i = 0; i < HID; i++) wg[i] = win[i] * g[i];
        const float4* xv = (const float4*)(xb + t);
#pragma unroll
        for (int s4 = 0; s4 < 4; s4++) {
            float4 xq = xv[s4];
            float xsv[4] = {xq.x, xq.y, xq.z, xq.w};
#pragma unroll
            for (int s = 0; s < 4; s++) {
#pragma unroll
                for (int i = 0; i < HID; i++)
                    h[i] = fmaf(A[i], h[i], xsv[s] * wg[i]);
                float yv = 0.0f;
#pragma unroll
                for (int i = 0; i < HID; i++) yv = fmaf(h[i], wo[i], yv);
                yb[t + s4 * 4 + s] = yv;
            }
        }
    }
}

extern "C" void kernel_launch(void* const* d_in, const int* in_sizes, int n_in,
                              void* d_out, int out_size) {
    const float* x    = (const float*)d_in[0];
    const float* w_in = (const float*)d_in[1];
    const float* w_out= (const float*)d_in[2];
    const float* w_ih = (const float*)d_in[3];
    const float* w_hh = (const float*)d_in[4];
    const float* b_ih = (const float*)d_in[5];
    const float* b_hh = (const float*)d_in[6];
    const float* w_sl = (const float*)d_in[7];
    const float* b_sl = (const float*)d_in[8];
    float* y = (float*)d_out;

    static int configured = 0;
    if (!configured) {
        cudaFuncSetAttribute(slow_wmma_kernel,
                             cudaFuncAttributeMaxDynamicSharedMemorySize, SM_BYTES);
        configured = 1;
    }

    init_cpar_kernel<<<1, GH>>>(w_ih, b_ih, b_hh);
    slow_wmma_kernel<<<2048, 256, SM_BYTES>>>(x, w_hh, w_sl, b_sl);
    pass1_kernel<<<(BB * NCH) / 256, 256>>>(x, w_in);
    scan_kernel<<<(BB * HID * 32) / 256, 256>>>();
    pass2_kernel<<<(BB * NCH) / 256, 256>>>(x, w_in, w_out, y);
}

// round 16
// speedup vs baseline: 1.0081x; 1.0081x over previous
#include <cuda_runtime.h>
#include <cuda_fp16.h>
#include <mma.h>
#include <math.h>
#include <stdint.h>

using namespace nvcuda;

#define BB   128
#define TT   65536
#define DELTA 16
#define LS   32
#define HID  8
#define GH   64
#define ODIM 16
#define FF   4095
#define CCH  64
#define NCH  (TT/CCH)

typedef unsigned int u32;

// ---------------- device scratch ----------------
__device__ float d_As[(size_t)BB * FF * HID];
__device__ float d_gs[(size_t)BB * FF * HID];
__device__ float d_P [BB * NCH * HID];
__device__ float d_c [BB * NCH * HID];
__device__ float d_H0[BB * NCH * HID];
__device__ float d_cpar[GH * 8];

__device__ __forceinline__ float sigf(float v) {
    return __fdividef(1.0f, 1.0f + __expf(-v));
}
__device__ __forceinline__ float tanh_ap(float v) {
    float r; asm("tanh.approx.f32 %0, %1;" : "=f"(r) : "f"(v)); return r;
}

// r,z entries pre-scaled by 0.5 so sigmoid = 0.5*tanh(acc)+0.5
__global__ void init_cpar_kernel(const float* __restrict__ w_ih,
                                 const float* __restrict__ b_ih,
                                 const float* __restrict__ b_hh) {
    int j = threadIdx.x;
    if (j < GH) {
        d_cpar[j*8+0] = 0.5f * w_ih[j];
        d_cpar[j*8+1] = 0.5f * w_ih[GH + j];
        d_cpar[j*8+2] = w_ih[2*GH + j];
        d_cpar[j*8+3] = 0.5f * (b_ih[j]      + b_hh[j]);
        d_cpar[j*8+4] = 0.5f * (b_ih[GH + j] + b_hh[GH + j]);
        d_cpar[j*8+5] = b_ih[2*GH + j];
        d_cpar[j*8+6] = b_hh[2*GH + j];
        d_cpar[j*8+7] = 0.0f;
    }
}

// ---------------- smem layout (bytes) ----------------
#define KAUG  80              // K padded: 64 h + bias lane(64) + xt lane(65) + zeros
#define LDW   88              // W row stride in halfs
#define LDHH  264             // H row stride in halfs
#define LDS_X2 34             // xs (fp16) row stride in halfs
#define SM_WHI  0                                   // 192*88*2 = 33792
#define SM_H    33792                               // 80*264*2 = 42240
#define SM_XS   (SM_H + KAUG*LDHH*2)                // 76032; 256*34*2 = 17408
#define SM_CPAR (SM_XS + 256*LDS_X2*2)              // 93440
#define SM_WSL  (SM_CPAR + GH*8*4)                  // 95488
#define SM_BSL  (SM_WSL + ODIM*GH*4)                // 99584
#define SM_BYTES (SM_BSL + 64)                      // 99648 (x2 = 199,296 fits)

// grid = 2048 CTAs, 256 threads, 2 CTAs/SM. CTA covers frames {2c, 2c+1} x 128 rows.
__global__ void __launch_bounds__(256, 2) slow_wmma_kernel(
    const float* __restrict__ x,
    const float* __restrict__ w_hh,
    const float* __restrict__ w_sl,
    const float* __restrict__ b_sl)
{
    extern __shared__ char sm[];
    const int tid  = threadIdx.x;
    const int wid  = tid >> 5;
    const int lane = tid & 31;
    const int f0   = blockIdx.x * 2;
    const int cb   = wid * 32;

    __half* WHI = (__half*)(sm + SM_WHI);
    __half* HS  = (__half*)(sm + SM_H);
    __half* xsh = (__half*)(sm + SM_XS);
    float* cparsm = (float*)(sm + SM_CPAR);
    float* wslsm  = (float*)(sm + SM_WSL);
    float* bslsm  = (float*)(sm + SM_BSL);

    // ---- probe wmma accumulator element->(row,col) mapping ----
    int jm[8], cm[8];
    {
        __half* pA = (__half*)(sm + SM_XS);
        __half* pB = pA + 256;
        if (tid < 256) {
            int r = tid >> 4, k = tid & 15;
            pA[tid] = __float2half_rn(r == k ? 1.0f : 0.0f);
            pB[tid] = __float2half_rn((float)tid);
        }
        __syncthreads();
        wmma::fragment<wmma::matrix_a, 16,16,16, __half, wmma::row_major> pa;
        wmma::fragment<wmma::matrix_b, 16,16,16, __half, wmma::row_major> pb;
        wmma::fragment<wmma::accumulator, 16,16,16, float> pc;
        wmma::load_matrix_sync(pa, pA, 16);
        wmma::load_matrix_sync(pb, pB, 16);
        wmma::fill_fragment(pc, 0.0f);
        wmma::mma_sync(pc, pa, pb, pc);
#pragma unroll
        for (int e = 0; e < 8; e++) {
            int v = (int)(pc.x[e] + 0.5f);
            jm[e] = v >> 4;
            cm[e] = v & 15;
        }
        __syncthreads();
    }

    // ---- prologue ----
    // Augmented W: col 64 = bias lane, col 65 = w_ih lane (r,z rows 0.5-scaled)
    for (int i = tid; i < 192 * LDW; i += 256) {
        int g = i / LDW, k = i % LDW;
        float v = 0.0f;
        if (k < 64) {
            v = w_hh[g * 64 + k];
            if (g < 128) v *= 0.5f;
        } else if (k == 64) {
            if (g < 64)       v = d_cpar[g * 8 + 3];
            else if (g < 128) v = d_cpar[(g - 64) * 8 + 4];
            else              v = d_cpar[(g - 128) * 8 + 6];
        } else if (k == 65) {
            if (g < 64)       v = d_cpar[g * 8 + 0];
            else if (g < 128) v = d_cpar[(g - 64) * 8 + 1];
        }
        WHI[g * LDW + k] = __float2half_rn(v);
    }
    // zero augmented H (80 rows), then set bias lane (row 64) to ones
    for (int i = tid; i < (KAUG * LDHH * 2) / 4; i += 256)
        ((u32*)(sm + SM_H))[i] = 0u;
    __syncthreads();
    if (tid < 256) HS[(size_t)64 * LDHH + tid] = __float2half_rn(1.0f);
    // stage x (fp16)
    {
        int c = tid;
        int b = c & 127;
        int f = f0 + (c >> 7); if (f > FF - 1) f = FF - 1;
        const float* xp = x + (size_t)b * TT + (size_t)f * DELTA;
#pragma unroll
        for (int t = 0; t < LS; t++) xsh[c * LDS_X2 + t] = __float2half_rn(xp[t]);
    }
    for (int i = tid; i < GH * 8;    i += 256) cparsm[i] = d_cpar[i];
    for (int i = tid; i < ODIM * GH; i += 256) wslsm[i]  = w_sl[i];
    if (tid < ODIM) bslsm[tid] = b_sl[tid];
    __syncthreads();

    // ---- 32 GRU steps ----
#pragma unroll 1
    for (int t = 0; t < LS; t++) {
        // refresh xt lane (row 65): lane l owns column cb+l
        HS[(size_t)65 * LDHH + (cb + lane)] = xsh[(cb + lane) * LDS_X2 + t];
        __syncwarp();

        // hoist xt (for n-gate inn) per lane's columns
        float xts[16];
#pragma unroll
        for (int e = 0; e < 8; e++) {
            xts[e]     = __half2float(xsh[(cb + cm[e]) * LDS_X2 + t]);
            xts[8 + e] = __half2float(xsh[(cb + 16 + cm[e]) * LDS_X2 + t]);
        }

        wmma::fragment<wmma::matrix_b, 16,16,16, __half, wmma::row_major> bF[5][2];
#pragma unroll
        for (int kt = 0; kt < 5; kt++)
#pragma unroll
            for (int nt = 0; nt < 2; nt++)
                wmma::load_matrix_sync(bF[kt][nt], HS + (size_t)(kt*16) * LDHH + cb + nt*16, LDHH);

#pragma unroll 1
        for (int mg = 0; mg < 4; mg++) {
            wmma::fragment<wmma::accumulator, 16,16,16, float> acc[3][2];
#pragma unroll
            for (int kind = 0; kind < 3; kind++)
#pragma unroll
                for (int nt = 0; nt < 2; nt++)
                    wmma::fill_fragment(acc[kind][nt], 0.0f);

#pragma unroll
            for (int kind = 0; kind < 3; kind++) {
                const int mi = kind * 4 + mg;
#pragma unroll
                for (int kt = 0; kt < 5; kt++) {
                    wmma::fragment<wmma::matrix_a, 16,16,16, __half, wmma::row_major> aHI;
                    wmma::load_matrix_sync(aHI, WHI + (size_t)(mi*16) * LDW + kt*16, LDW);
                    wmma::mma_sync(acc[kind][0], aHI, bF[kt][0], acc[kind][0]);
                    wmma::mma_sync(acc[kind][1], aHI, bF[kt][1], acc[kind][1]);
                }
            }

            // epilogue: acc IS the pre-activation (bias + x-term folded into MMA)
#pragma unroll
            for (int e = 0; e < 8; e++) {
                const int j = mg * 16 + jm[e];
                const float cwn = cparsm[j * 8 + 2];
                const float cbi = cparsm[j * 8 + 5];
#pragma unroll
                for (int nt = 0; nt < 2; nt++) {
                    const int c = cb + nt * 16 + cm[e];
                    const float xt = xts[nt * 8 + e];

                    float ho = __half2float(HS[(size_t)j * LDHH + c]);

                    float r = fmaf(tanh_ap(acc[0][nt].x[e]), 0.5f, 0.5f);
                    float z = fmaf(tanh_ap(acc[1][nt].x[e]), 0.5f, 0.5f);
                    float inn = fmaf(xt, cwn, cbi);
                    float n = tanh_ap(fmaf(r, acc[2][nt].x[e], inn));
                    float h = fmaf(z, ho - n, n);

                    HS[(size_t)j * LDHH + c] = __float2half_rn(h);
                }
            }
        }
        __syncwarp();
    }

    // ---- final projection (accurate sigmoid) ----
    {
        const int c = tid;
        const int b = c & 127;
        const int f = f0 + (c >> 7);
        if (f < FF) {
            float hv[GH];
#pragma unroll
            for (int k = 0; k < GH; k++)
                hv[k] = __half2float(HS[(size_t)k * LDHH + c]);
            const size_t ob = ((size_t)b * FF + f) * HID;
#pragma unroll 1
            for (int o = 0; o < HID; o++) {
                float a0 = bslsm[o];
                float a1 = bslsm[HID + o];
#pragma unroll
                for (int k = 0; k < GH; k++) {
                    a0 = fmaf(wslsm[o * GH + k], hv[k], a0);
                    a1 = fmaf(wslsm[(HID + o) * GH + k], hv[k], a1);
                }
                d_As[ob + o] = sigf(a0);
                d_gs[ob + o] = a1;
            }
        }
    }
}

// ---------------- fast branch ----------------
__global__ void __launch_bounds__(256) pass1_kernel(
    const float* __restrict__ x, const float* __restrict__ w_in)
{
    int q = blockIdx.x * blockDim.x + threadIdx.x;
    if (q >= BB * NCH) return;
    int b = q / NCH, ch = q % NCH;
    float win[HID], P[HID], c[HID];
#pragma unroll
    for (int i = 0; i < HID; i++) { win[i] = w_in[i]; P[i] = 1.0f; c[i] = 0.0f; }
    const int t0 = ch * CCH;
    const float* xb = x + (size_t)b * TT;
#pragma unroll 1
    for (int blk = 0; blk < CCH / 16; blk++) {
        int t = t0 + blk * 16;
        int j = (t >> 4) - 1; if (j < 0) j = 0;
        const float4* ap = (const float4*)(d_As + ((size_t)b * FF + j) * HID);
        const float4* gp = (const float4*)(d_gs + ((size_t)b * FF + j) * HID);
        float4 Aa = ap[0], Ab = ap[1], ga = gp[0], gb2 = gp[1];
        float A[HID] = {Aa.x, Aa.y, Aa.z, Aa.w, Ab.x, Ab.y, Ab.z, Ab.w};
        float g[HID] = {ga.x, ga.y, ga.z, ga.w, gb2.x, gb2.y, gb2.z, gb2.w};
        float wg[HID], a16[HID];
#pragma unroll
        for (int i = 0; i < HID; i++) {
            wg[i] = win[i] * g[i];
            float a2 = A[i]*A[i], a4 = a2*a2, a8 = a4*a4;
            a16[i] = a8*a8;
        }
        const float4* xv = (const float4*)(xb + t);
#pragma unroll
        for (int s4 = 0; s4 < 4; s4++) {
            float4 xq = xv[s4];
            float xsv[4] = {xq.x, xq.y, xq.z, xq.w};
#pragma unroll
            for (int s = 0; s < 4; s++)
#pragma unroll
                for (int i = 0; i < HID; i++)
                    c[i] = fmaf(A[i], c[i], xsv[s] * wg[i]);
        }
#pragma unroll
        for (int i = 0; i < HID; i++) P[i] *= a16[i];
    }
    const size_t base = ((size_t)b * NCH + ch) * HID;
#pragma unroll
    for (int i = 0; i < HID; i++) { d_P[base + i] = P[i]; d_c[base + i] = c[i]; }
}

__global__ void __launch_bounds__(256) scan_kernel() {
    int gw   = (blockIdx.x * blockDim.x + threadIdx.x) >> 5;
    int lane = threadIdx.x & 31;
    int b = gw >> 3, i = gw & 7;
    const int S = NCH / 32;
    float P[S], c[S];
#pragma unroll
    for (int s = 0; s < S; s++) {
        size_t idx = ((size_t)b * NCH + (lane * S + s)) * HID + i;
        P[s] = d_P[idx]; c[s] = d_c[idx];
    }
    float Pt = 1.0f, ct = 0.0f;
#pragma unroll
    for (int s = 0; s < S; s++) { ct = fmaf(P[s], ct, c[s]); Pt *= P[s]; }
#pragma unroll
    for (int off = 1; off < 32; off <<= 1) {
        float Pp = __shfl_up_sync(0xffffffffu, Pt, off);
        float cp = __shfl_up_sync(0xffffffffu, ct, off);
        if (lane >= off) { ct = fmaf(Pt, cp, ct); Pt *= Pp; }
    }
    float h = __shfl_up_sync(0xffffffffu, ct, 1);
    if (lane == 0) h = 0.0f;
#pragma unroll
    for (int s = 0; s < S; s++) {
        size_t idx = ((size_t)b * NCH + (lane * S + s)) * HID + i;
        d_H0[idx] = h;
        h = fmaf(P[s], h, c[s]);
    }
}

__global__ void __launch_bounds__(256) pass2_kernel(
    const float* __restrict__ x, const float* __restrict__ w_in,
    const float* __restrict__ w_out, float* __restrict__ y)
{
    int q = blockIdx.x * blockDim.x + threadIdx.x;
    if (q >= BB * NCH) return;
    int b = q / NCH, ch = q % NCH;
    float win[HID], wo[HID], h[HID];
#pragma unroll
    for (int i = 0; i < HID; i++) {
        win[i] = w_in[i]; wo[i] = w_out[i];
        h[i] = d_H0[((size_t)b * NCH + ch) * HID + i];
    }
    const int t0 = ch * CCH;
    const float* xb = x + (size_t)b * TT;
    float* yb = y + (size_t)b * TT;
#pragma unroll 1
    for (int blk = 0; blk < CCH / 16; blk++) {
        int t = t0 + blk * 16;
        int j = (t >> 4) - 1; if (j < 0) j = 0;
        const float4* ap = (const float4*)(d_As + ((size_t)b * FF + j) * HID);
        const float4* gp = (const float4*)(d_gs + ((size_t)b * FF + j) * HID);
        float4 Aa = ap[0], Ab = ap[1], ga = gp[0], gb2 = gp[1];
        float A[HID] = {Aa.x, Aa.y, Aa.z, Aa.w, Ab.x, Ab.y, Ab.z, Ab.w};
        float g[HID] = {ga.x, ga.y, ga.z, ga.w, gb2.x, gb2.y, gb2.z, gb2.w};
        float wg[HID];
#pragma unroll
        for (int i = 0; i < HID; i++) wg[i] = win[i] * g[i];
        const float4* xv = (const float4*)(xb + t);
#pragma unroll
        for (int s4 = 0; s4 < 4; s4++) {
            float4 xq = xv[s4];
            float xsv[4] = {xq.x, xq.y, xq.z, xq.w};
#pragma unroll
            for (int s = 0; s < 4; s++) {
#pragma unroll
                for (int i = 0; i < HID; i++)
                    h[i] = fmaf(A[i], h[i], xsv[s] * wg[i]);
                float yv = 0.0f;
#pragma unroll
                for (int i = 0; i < HID; i++) yv = fmaf(h[i], wo[i], yv);
                yb[t + s4 * 4 + s] = yv;
            }
        }
    }
}

extern "C" void kernel_launch(void* const* d_in, const int* in_sizes, int n_in,
                              void* d_out, int out_size) {
    const float* x    = (const float*)d_in[0];
    const float* w_in = (const float*)d_in[1];
    const float* w_out= (const float*)d_in[2];
    const float* w_ih = (const float*)d_in[3];
    const float* w_hh = (const float*)d_in[4];
    const float* b_ih = (const float*)d_in[5];
    const float* b_hh = (const float*)d_in[6];
    const float* w_sl = (const float*)d_in[7];
    const float* b_sl = (const float*)d_in[8];
    float* y = (float*)d_out;

    static int configured = 0;
    if (!configured) {
        cudaFuncSetAttribute(slow_wmma_kernel,
                             cudaFuncAttributeMaxDynamicSharedMemorySize, SM_BYTES);
        configured = 1;
    }

    init_cpar_kernel<<<1, GH>>>(w_ih, b_ih, b_hh);
    slow_wmma_kernel<<<2048, 256, SM_BYTES>>>(x, w_hh, w_sl, b_sl);
    pass1_kernel<<<(BB * NCH) / 256, 256>>>(x, w_in);
    scan_kernel<<<(BB * HID * 32) / 256, 256>>>();
    pass2_kernel<<<(BB * NCH) / 256, 256>>>(x, w_in, w_out, y);
}

// round 17
// speedup vs baseline: 1.0175x; 1.0093x over previous
#include <cuda_runtime.h>
#include <cuda_fp16.h>
#include <mma.h>
#include <math.h>
#include <stdint.h>

using namespace nvcuda;

#define BB   128
#define TT   65536
#define DELTA 16
#define LS   32
#define HID  8
#define GH   64
#define ODIM 16
#define FF   4095
#define CCH  64
#define NCH  (TT/CCH)

typedef unsigned int u32;

// ---------------- device scratch ----------------
__device__ float d_As[(size_t)BB * FF * HID];
__device__ float d_gs[(size_t)BB * FF * HID];
__device__ float d_P [BB * NCH * HID];
__device__ float d_c [BB * NCH * HID];
__device__ float d_H0[BB * NCH * HID];
__device__ float d_cpar[GH * 8];

__device__ __forceinline__ float sigf(float v) {
    return __fdividef(1.0f, 1.0f + __expf(-v));
}
__device__ __forceinline__ float tanh_ap(float v) {
    float r; asm("tanh.approx.f32 %0, %1;" : "=f"(r) : "f"(v)); return r;
}
__device__ __forceinline__ float sig_ap(float v) {
    return fmaf(tanh_ap(0.5f * v), 0.5f, 0.5f);
}

__global__ void init_cpar_kernel(const float* __restrict__ w_ih,
                                 const float* __restrict__ b_ih,
                                 const float* __restrict__ b_hh) {
    int j = threadIdx.x;
    if (j < GH) {
        d_cpar[j*8+0] = w_ih[j];
        d_cpar[j*8+1] = w_ih[GH + j];
        d_cpar[j*8+2] = w_ih[2*GH + j];
        d_cpar[j*8+3] = b_ih[j]      + b_hh[j];
        d_cpar[j*8+4] = b_ih[GH + j] + b_hh[GH + j];
        d_cpar[j*8+5] = b_ih[2*GH + j];
        d_cpar[j*8+6] = b_hh[2*GH + j];
        d_cpar[j*8+7] = 0.0f;
    }
}

// ---------------- smem layout (bytes) ----------------
#define LDW   72
#define LDHH  264
#define LDS_X 33
#define SM_WHI  0
#define SM_H    (SM_WHI + 192*LDW*2)         // 27648
#define SM_XS   (SM_H + 64*LDHH*2)           // 61440
#define SM_CPAR (SM_XS + 256*LDS_X*4)        // 95232
#define SM_WSL  (SM_CPAR + GH*8*4)           // 97280
#define SM_BSL  (SM_WSL + ODIM*GH*4)         // 101376
#define SM_BYTES (SM_BSL + 64)               // 101440 (x2 fits 228KB/SM)

// grid = 2048 CTAs, 256 threads, 2 CTAs/SM. CTA covers frames {2c, 2c+1} x 128 rows.
__global__ void __launch_bounds__(256, 2) slow_wmma_kernel(
    const float* __restrict__ x,
    const float* __restrict__ w_hh,
    const float* __restrict__ w_sl,
    const float* __restrict__ b_sl)
{
    extern __shared__ char sm[];
    const int tid  = threadIdx.x;
    const int wid  = tid >> 5;
    const int f0   = blockIdx.x * 2;
    const int cb   = wid * 32;

    __half* WHI = (__half*)(sm + SM_WHI);
    __half* HS  = (__half*)(sm + SM_H);
    float* xs     = (float*)(sm + SM_XS);
    float* cparsm = (float*)(sm + SM_CPAR);
    float* wslsm  = (float*)(sm + SM_WSL);
    float* bslsm  = (float*)(sm + SM_BSL);

    // ---- probe wmma accumulator element->(row,col) mapping ----
    int jm[8], cm[8];
    {
        __half* pA = (__half*)(sm + SM_XS);
        __half* pB = pA + 256;
        if (tid < 256) {
            int r = tid >> 4, k = tid & 15;
            pA[tid] = __float2half_rn(r == k ? 1.0f : 0.0f);
            pB[tid] = __float2half_rn((float)tid);
        }
        __syncthreads();
        wmma::fragment<wmma::matrix_a, 16,16,16, __half, wmma::row_major> pa;
        wmma::fragment<wmma::matrix_b, 16,16,16, __half, wmma::row_major> pb;
        wmma::fragment<wmma::accumulator, 16,16,16, float> pc;
        wmma::load_matrix_sync(pa, pA, 16);
        wmma::load_matrix_sync(pb, pB, 16);
        wmma::fill_fragment(pc, 0.0f);
        wmma::mma_sync(pc, pa, pb, pc);
#pragma unroll
        for (int e = 0; e < 8; e++) {
            int v = (int)(pc.x[e] + 0.5f);
            jm[e] = v >> 4;
            cm[e] = v & 15;
        }
        __syncthreads();
    }

    // ---- prologue ----
    for (int i = tid; i < 192 * GH; i += 256) {
        int g = i >> 6, k = i & 63;
        WHI[g * LDW + k] = __float2half_rn(w_hh[i]);
    }
    for (int i = tid; i < (64 * LDHH * 2) / 4; i += 256)
        ((u32*)(sm + SM_H))[i] = 0u;
    {
        int c = tid;
        int b = c & 127;
        int f = f0 + (c >> 7); if (f > FF - 1) f = FF - 1;
        const float* xp = x + (size_t)b * TT + (size_t)f * DELTA;
#pragma unroll
        for (int t = 0; t < LS; t++) xs[c * LDS_X + t] = xp[t];
    }
    for (int i = tid; i < GH * 8;    i += 256) cparsm[i] = d_cpar[i];
    for (int i = tid; i < ODIM * GH; i += 256) wslsm[i]  = w_sl[i];
    if (tid < ODIM) bslsm[tid] = b_sl[tid];
    __syncthreads();

    // register-carried h state: hreg[mg*8+e] = (h at nt=0, h at nt=1), rounded fp16
    __half2 hreg[32];
#pragma unroll
    for (int i = 0; i < 32; i++) hreg[i] = __floats2half2_rn(0.0f, 0.0f);

    // ---- 32 GRU steps ----
#pragma unroll 1
    for (int t = 0; t < LS; t++) {
        float xts[16];
#pragma unroll
        for (int e = 0; e < 8; e++) {
            xts[e]     = xs[(cb + cm[e]) * LDS_X + t];
            xts[8 + e] = xs[(cb + 16 + cm[e]) * LDS_X + t];
        }

        wmma::fragment<wmma::matrix_b, 16,16,16, __half, wmma::row_major> bF[4][2];
#pragma unroll
        for (int kt = 0; kt < 4; kt++)
#pragma unroll
            for (int nt = 0; nt < 2; nt++)
                wmma::load_matrix_sync(bF[kt][nt], HS + (size_t)(kt*16) * LDHH + cb + nt*16, LDHH);

#pragma unroll 1
        for (int mg = 0; mg < 4; mg++) {
            wmma::fragment<wmma::accumulator, 16,16,16, float> acc[3][2];
#pragma unroll
            for (int kind = 0; kind < 3; kind++)
#pragma unroll
                for (int nt = 0; nt < 2; nt++)
                    wmma::fill_fragment(acc[kind][nt], 0.0f);

#pragma unroll
            for (int kind = 0; kind < 3; kind++) {
                const int mi = kind * 4 + mg;
#pragma unroll
                for (int kt = 0; kt < 4; kt++) {
                    wmma::fragment<wmma::matrix_a, 16,16,16, __half, wmma::row_major> aHI;
                    wmma::load_matrix_sync(aHI, WHI + (size_t)(mi*16) * LDW + kt*16, LDW);
                    wmma::mma_sync(acc[kind][0], aHI, bF[kt][0], acc[kind][0]);
                    wmma::mma_sync(acc[kind][1], aHI, bF[kt][1], acc[kind][1]);
                }
            }

            // fragment-direct epilogue; ho from carried registers (no HS loads)
#pragma unroll
            for (int e = 0; e < 8; e++) {
                const int j = mg * 16 + jm[e];
                const float4 c0 = ((const float4*)(cparsm + j * 8))[0];
                const float4 c1 = ((const float4*)(cparsm + j * 8))[1];
                const int ca = cb + cm[e];
                const int cn = cb + 16 + cm[e];

                __half2 hold = hreg[mg * 8 + e];
                float ho0 = __low2float(hold);
                float ho1 = __high2float(hold);

                float r0 = sig_ap(acc[0][0].x[e] + fmaf(xts[e], c0.x, c0.w));
                float z0 = sig_ap(acc[1][0].x[e] + fmaf(xts[e], c0.y, c1.x));
                float n0 = tanh_ap(fmaf(xts[e], c0.z, c1.y) + r0 * (acc[2][0].x[e] + c1.z));
                float h0 = n0 + z0 * (ho0 - n0);

                float r1 = sig_ap(acc[0][1].x[e] + fmaf(xts[8+e], c0.x, c0.w));
                float z1 = sig_ap(acc[1][1].x[e] + fmaf(xts[8+e], c0.y, c1.x));
                float n1 = tanh_ap(fmaf(xts[8+e], c0.z, c1.y) + r1 * (acc[2][1].x[e] + c1.z));
                float h1 = n1 + z1 * (ho1 - n1);

                __half s0 = __float2half_rn(h0);
                __half s1 = __float2half_rn(h1);
                HS[(size_t)j * LDHH + ca] = s0;
                HS[(size_t)j * LDHH + cn] = s1;
                hreg[mg * 8 + e] = __halves2half2(s0, s1);
            }
        }
        __syncwarp();
    }

    // ---- final projection (accurate sigmoid) ----
    {
        const int c = tid;
        const int b = c & 127;
        const int f = f0 + (c >> 7);
        if (f < FF) {
            float hv[GH];
#pragma unroll
            for (int k = 0; k < GH; k++)
                hv[k] = __half2float(HS[(size_t)k * LDHH + c]);
            const size_t ob = ((size_t)b * FF + f) * HID;
#pragma unroll 1
            for (int o = 0; o < HID; o++) {
                float a0 = bslsm[o];
                float a1 = bslsm[HID + o];
#pragma unroll
                for (int k = 0; k < GH; k++) {
                    a0 = fmaf(wslsm[o * GH + k], hv[k], a0);
                    a1 = fmaf(wslsm[(HID + o) * GH + k], hv[k], a1);
                }
                d_As[ob + o] = sigf(a0);
                d_gs[ob + o] = a1;
            }
        }
    }
}

// ---------------- fast branch ----------------
__global__ void __launch_bounds__(256) pass1_kernel(
    const float* __restrict__ x, const float* __restrict__ w_in)
{
    int q = blockIdx.x * blockDim.x + threadIdx.x;
    if (q >= BB * NCH) return;
    int b = q / NCH, ch = q % NCH;
    float win[HID], P[HID], c[HID];
#pragma unroll
    for (int i = 0; i < HID; i++) { win[i] = w_in[i]; P[i] = 1.0f; c[i] = 0.0f; }
    const int t0 = ch * CCH;
    const float* xb = x + (size_t)b * TT;
#pragma unroll 1
    for (int blk = 0; blk < CCH / 16; blk++) {
        int t = t0 + blk * 16;
        int j = (t >> 4) - 1; if (j < 0) j = 0;
        const float4* ap = (const float4*)(d_As + ((size_t)b * FF + j) * HID);
        const float4* gp = (const float4*)(d_gs + ((size_t)b * FF + j) * HID);
        float4 Aa = ap[0], Ab = ap[1], ga = gp[0], gb2 = gp[1];
        float A[HID] = {Aa.x, Aa.y, Aa.z, Aa.w, Ab.x, Ab.y, Ab.z, Ab.w};
        float g[HID] = {ga.x, ga.y, ga.z, ga.w, gb2.x, gb2.y, gb2.z, gb2.w};
        float wg[HID], a16[HID];
#pragma unroll
        for (int i = 0; i < HID; i++) {
            wg[i] = win[i] * g[i];
            float a2 = A[i]*A[i], a4 = a2*a2, a8 = a4*a4;
            a16[i] = a8*a8;
        }
        const float4* xv = (const float4*)(xb + t);
#pragma unroll
        for (int s4 = 0; s4 < 4; s4++) {
            float4 xq = xv[s4];
            float xsv[4] = {xq.x, xq.y, xq.z, xq.w};
#pragma unroll
            for (int s = 0; s < 4; s++)
#pragma unroll
                for (int i = 0; i < HID; i++)
                    c[i] = fmaf(A[i], c[i], xsv[s] * wg[i]);
        }
#pragma unroll
        for (int i = 0; i < HID; i++) P[i] *= a16[i];
    }
    const size_t base = ((size_t)b * NCH + ch) * HID;
#pragma unroll
    for (int i = 0; i < HID; i++) { d_P[base + i] = P[i]; d_c[base + i] = c[i]; }
}

__global__ void __launch_bounds__(256) scan_kernel() {
    int gw   = (blockIdx.x * blockDim.x + threadIdx.x) >> 5;
    int lane = threadIdx.x & 31;
    int b = gw >> 3, i = gw & 7;
    const int S = NCH / 32;
    float P[S], c[S];
#pragma unroll
    for (int s = 0; s < S; s++) {
        size_t idx = ((size_t)b * NCH + (lane * S + s)) * HID + i;
        P[s] = d_P[idx]; c[s] = d_c[idx];
    }
    float Pt = 1.0f, ct = 0.0f;
#pragma unroll
    for (int s = 0; s < S; s++) { ct = fmaf(P[s], ct, c[s]); Pt *= P[s]; }
#pragma unroll
    for (int off = 1; off < 32; off <<= 1) {
        float Pp = __shfl_up_sync(0xffffffffu, Pt, off);
        float cp = __shfl_up_sync(0xffffffffu, ct, off);
        if (lane >= off) { ct = fmaf(Pt, cp, ct); Pt *= Pp; }
    }
    float h = __shfl_up_sync(0xffffffffu, ct, 1);
    if (lane == 0) h = 0.0f;
#pragma unroll
    for (int s = 0; s < S; s++) {
        size_t idx = ((size_t)b * NCH + (lane * S + s)) * HID + i;
        d_H0[idx] = h;
        h = fmaf(P[s], h, c[s]);
    }
}

__global__ void __launch_bounds__(256) pass2_kernel(
    const float* __restrict__ x, const float* __restrict__ w_in,
    const float* __restrict__ w_out, float* __restrict__ y)
{
    int q = blockIdx.x * blockDim.x + threadIdx.x;
    if (q >= BB * NCH) return;
    int b = q / NCH, ch = q % NCH;
    float win[HID], wo[HID], h[HID];
#pragma unroll
    for (int i = 0; i < HID; i++) {
        win[i] = w_in[i]; wo[i] = w_out[i];
        h[i] = d_H0[((size_t)b * NCH + ch) * HID + i];
    }
    const int t0 = ch * CCH;
    const float* xb = x + (size_t)b * TT;
    float* yb = y + (size_t)b * TT;
#pragma unroll 1
    for (int blk = 0; blk < CCH / 16; blk++) {
        int t = t0 + blk * 16;
        int j = (t >> 4) - 1; if (j < 0) j = 0;
        const float4* ap = (const float4*)(d_As + ((size_t)b * FF + j) * HID);
        const float4* gp = (const float4*)(d_gs + ((size_t)b * FF + j) * HID);
        float4 Aa = ap[0], Ab = ap[1], ga = gp[0], gb2 = gp[1];
        float A[HID] = {Aa.x, Aa.y, Aa.z, Aa.w, Ab.x, Ab.y, Ab.z, Ab.w};
        float g[HID] = {ga.x, ga.y, ga.z, ga.w, gb2.x, gb2.y, gb2.z, gb2.w};
        float wg[HID];
#pragma unroll
        for (int i = 0; i < HID; i++) wg[i] = win[i] * g[i];
        const float4* xv = (const float4*)(xb + t);
#pragma unroll
        for (int s4 = 0; s4 < 4; s4++) {
            float4 xq = xv[s4];
            float xsv[4] = {xq.x, xq.y, xq.z, xq.w};
#pragma unroll
            for (int s = 0; s < 4; s++) {
#pragma unroll
                for (int i = 0; i < HID; i++)
                    h[i] = fmaf(A[i], h[i], xsv[s] * wg[i]);
                float yv = 0.0f;
#pragma unroll
                for (int i = 0; i < HID; i++) yv = fmaf(h[i], wo[i], yv);
                yb[t + s4 * 4 + s] = yv;
            }
        }
    }
}

extern "C" void kernel_launch(void* const* d_in, const int* in_sizes, int n_in,
                              void* d_out, int out_size) {
    const float* x    = (const float*)d_in[0];
    const float* w_in = (const float*)d_in[1];
    const float* w_out= (const float*)d_in[2];
    const float* w_ih = (const float*)d_in[3];
    const float* w_hh = (const float*)d_in[4];
    const float* b_ih = (const float*)d_in[5];
    const float* b_hh = (const float*)d_in[6];
    const float* w_sl = (const float*)d_in[7];
    const float* b_sl = (const float*)d_in[8];
    float* y = (float*)d_out;

    static int configured = 0;
    if (!configured) {
        cudaFuncSetAttribute(slow_wmma_kernel,
                             cudaFuncAttributeMaxDynamicSharedMemorySize, SM_BYTES);
        configured = 1;
    }

    init_cpar_kernel<<<1, GH>>>(w_ih, b_ih, b_hh);
    slow_wmma_kernel<<<2048, 256, SM_BYTES>>>(x, w_hh, w_sl, b_sl);
    pass1_kernel<<<(BB * NCH) / 256, 256>>>(x, w_in);
    scan_kernel<<<(BB * HID * 32) / 256, 256>>>();
    pass2_kernel<<<(BB * NCH) / 256, 256>>>(x, w_in, w_out, y);
}